// round 14
// baseline (speedup 1.0000x reference)
#include <cuda_runtime.h>
#include <cuda_fp16.h>
#include <cstdint>

// ---------------------------------------------------------------------------
// Problem constants
// ---------------------------------------------------------------------------
#define BSZ   8
#define TLEN  4096
#define HDIM  1024
#define N3H   3072
#define KSZ   1024
#define MROWS (BSZ * TLEN)      // 32768
#define NC    64                // scan chunks per sequence
#define CL    (TLEN / NC)       // 64 steps per chunk

// ---------------------------------------------------------------------------
// Device scratch (no allocations allowed)
// ---------------------------------------------------------------------------
__device__ __half g_z [(size_t)MROWS * N3H];      // transformed gates (fp16)
                                                  // [0..1023]=gv [1024..2047]=cf [2048..]=gp
__device__ __half g_af[(size_t)MROWS * KSZ];      // A fp16 [M,K]; also inter-layer h
__device__ __half g_w0[(size_t)N3H * KSZ];        // W0^T fp16 [N,K]
__device__ __half g_w1[(size_t)N3H * KSZ];        // W1^T fp16 [N,K]
__device__ float  g_cP[(size_t)BSZ * NC * HDIM];  // chunk coeff product
__device__ float  g_cS[(size_t)BSZ * NC * HDIM];  // chunk local scan end

// ---------------------------------------------------------------------------
// Helpers
// ---------------------------------------------------------------------------
__device__ __forceinline__ uint32_t smem_u32(const void* p) {
    uint32_t a;
    asm("{ .reg .u64 t; cvta.to.shared.u64 t, %1; cvt.u32.u64 %0, t; }"
        : "=r"(a) : "l"(p));
    return a;
}

__device__ __forceinline__ void cp16(uint32_t dst, const void* src) {
    asm volatile("cp.async.cg.shared.global [%0], [%1], 16;" :: "r"(dst), "l"(src));
}

__device__ __forceinline__ void ldsm4(uint32_t r[4], uint32_t addr) {
    asm volatile("ldmatrix.sync.aligned.m8n8.x4.shared.b16 {%0,%1,%2,%3}, [%4];"
        : "=r"(r[0]), "=r"(r[1]), "=r"(r[2]), "=r"(r[3]) : "r"(addr));
}

__device__ __forceinline__ void mma_f16(float c[4], const uint32_t a[4],
                                        uint32_t b0, uint32_t b1) {
    asm volatile(
        "mma.sync.aligned.m16n8k16.row.col.f32.f16.f16.f32 "
        "{%0,%1,%2,%3}, {%4,%5,%6,%7}, {%8,%9}, {%0,%1,%2,%3};"
        : "+f"(c[0]), "+f"(c[1]), "+f"(c[2]), "+f"(c[3])
        : "r"(a[0]), "r"(a[1]), "r"(a[2]), "r"(a[3]), "r"(b0), "r"(b1));
}

__device__ __forceinline__ float fsig(float x) {
    return __fdividef(1.0f, 1.0f + __expf(-x));
}

// per-section gate transform (GEMM epilogue)
__device__ __forceinline__ float gate_xform(float v, int mode) {
    if (mode == 0) return (v >= 0.0f) ? (v + 0.5f) : fsig(v);
    if (mode == 1) return __fdividef(1.0f, 1.0f + __expf(v));
    return fsig(v);
}

// ---------------------------------------------------------------------------
// GEMM: z'[M,3H] = xform(A[M,K] * W[K,3H]), fp16 in, fp32 acc, fp16 out.
// Tile 128x128, BK=64, 3-stage cp.async, 8 warps x (64x32), 2 CTAs/SM.
// ---------------------------------------------------------------------------
#define GM_BM 128
#define GM_BN 128
#define GM_BK 64
#define STAGES 3
#define KITERS (KSZ / GM_BK)            // 16
#define OPB 16384                       // operand tile: 128 rows x 128 B
#define STB (2 * OPB)                   // stage: A,B = 32 KB
#define SMEM_DYN (STAGES * STB)         // 96 KB

// smem offset within an operand tile for (k16-slice 0..3, row, 16B-group)
__device__ __forceinline__ uint32_t sw_off(int slice, int r, int g) {
    return (uint32_t)(((slice * 128 + r) * 2 + (g ^ ((r >> 2) & 1))) * 16);
}

__device__ __forceinline__ void load_stage(
    uint32_t sbase, int stage,
    const __half* __restrict__ A, const __half* __restrict__ B,
    int bm, int bn, int kt, int tid)
{
    const int k0 = kt * GM_BK;
    const uint32_t st = sbase + (uint32_t)stage * STB;
    #pragma unroll
    for (int i = 0; i < 8; ++i) {
        const int idx = tid + i * 256;          // 0 .. 2047
        const int op = idx >> 10;               // 0=A 1=B
        const int j = idx & 1023;
        const int r = j >> 3, slice = (j >> 1) & 3, g = j & 1;
        const __half* base = op ? B : A;
        const int grow = (op ? bn : bm) + r;
        const void* src = base + (size_t)grow * KSZ + k0 + slice * 16 + g * 8;
        cp16(st + (uint32_t)op * OPB + sw_off(slice, r, g), src);
    }
    asm volatile("cp.async.commit_group;" ::: "memory");
}

__global__ void __launch_bounds__(256, 2)
gemm_f16(const __half* __restrict__ A, const __half* __restrict__ B,
         __half* __restrict__ C)
{
    extern __shared__ char dsm[];
    const uint32_t sbase = smem_u32(dsm);

    const int tid  = threadIdx.x;
    const int lane = tid & 31;
    const int wid  = tid >> 5;
    const int wm   = wid >> 2;
    const int wn   = wid & 3;
    const int bm   = blockIdx.y * GM_BM;
    const int bn   = blockIdx.x * GM_BN;

    const int rowA = (lane & 7) + ((lane >> 3) & 1) * 8;
    const int gA   = lane >> 4;
    const int rowB = (lane & 7) + (lane >> 4) * 8;
    const int gB   = (lane >> 3) & 1;

    float acc[4][4][4];
    #pragma unroll
    for (int i = 0; i < 4; ++i)
        #pragma unroll
        for (int j = 0; j < 4; ++j)
            #pragma unroll
            for (int q = 0; q < 4; ++q) acc[i][j][q] = 0.0f;

    #pragma unroll
    for (int s = 0; s < STAGES - 1; ++s)
        load_stage(sbase, s, A, B, bm, bn, s, tid);

    int cur = 0, nxt = STAGES - 1;
    for (int kt = 0; kt < KITERS; ++kt) {
        asm volatile("cp.async.wait_group %0;" :: "n"(STAGES - 2) : "memory");
        __syncthreads();

        if (kt + STAGES - 1 < KITERS) {
            load_stage(sbase, nxt, A, B, bm, bn, kt + STAGES - 1, tid);
            if (++nxt == STAGES) nxt = 0;
        }

        const uint32_t st = sbase + (uint32_t)cur * STB;
        if (++cur == STAGES) cur = 0;

        #pragma unroll
        for (int slice = 0; slice < 4; ++slice) {
            uint32_t af[4][4];
            #pragma unroll
            for (int mf = 0; mf < 4; ++mf) {
                const uint32_t off = sw_off(slice, wm * 64 + mf * 16 + rowA, gA);
                ldsm4(af[mf], st + off);
            }
            #pragma unroll
            for (int n16 = 0; n16 < 2; ++n16) {
                uint32_t bf[4];
                const uint32_t offB = sw_off(slice, wn * 32 + n16 * 16 + rowB, gB);
                ldsm4(bf, st + OPB + offB);
                #pragma unroll
                for (int mf = 0; mf < 4; ++mf)
                    #pragma unroll
                    for (int h = 0; h < 2; ++h)
                        mma_f16(acc[mf][n16 * 2 + h], af[mf],
                                bf[2 * h], bf[2 * h + 1]);
            }
        }
    }

    const int mode = bn >> 10;           // 0=hidden 1=gate 2=proj
    #pragma unroll
    for (int mf = 0; mf < 4; ++mf) {
        const int row = bm + wm * 64 + mf * 16 + (lane >> 2);
        #pragma unroll
        for (int nf = 0; nf < 4; ++nf) {
            const float* c = acc[mf][nf];
            const int col = bn + wn * 32 + (nf >> 1) * 16 + (nf & 1) * 8 + (lane & 3) * 2;
            float t0 = gate_xform(c[0], mode), t1 = gate_xform(c[1], mode);
            float t2 = gate_xform(c[2], mode), t3 = gate_xform(c[3], mode);
            *(__half2*)(C + (size_t)row * N3H + col)       = __floats2half2_rn(t0, t1);
            *(__half2*)(C + (size_t)(row + 8) * N3H + col) = __floats2half2_rn(t2, t3);
        }
    }
}

// ---------------------------------------------------------------------------
// Fused prologue: transpose+convert W0 and W1, convert A -> fp16.
// ---------------------------------------------------------------------------
#define WT_BLOCKS 3072
#define CA_BLOCKS 32768

__global__ void __launch_bounds__(256)
prep_kernel(const float* __restrict__ W0, const float* __restrict__ W1,
            const float* __restrict__ h,
            __half* __restrict__ w0t, __half* __restrict__ w1t,
            __half* __restrict__ af)
{
    const int bi = blockIdx.x;
    if (bi < 2 * WT_BLOCKS) {
        __shared__ float tile[32][33];
        const float* W = (bi < WT_BLOCKS) ? W0 : W1;
        __half* o = (bi < WT_BLOCKS) ? w0t : w1t;
        const int lb = (bi < WT_BLOCKS) ? bi : bi - WT_BLOCKS;
        const int n0 = (lb % 96) * 32;
        const int k0 = (lb / 96) * 32;
        const int tx = threadIdx.x & 31, ty = threadIdx.x >> 5;
        #pragma unroll
        for (int r = ty; r < 32; r += 8)
            tile[r][tx] = W[(size_t)(k0 + r) * N3H + n0 + tx];
        __syncthreads();
        #pragma unroll
        for (int r = ty; r < 32; r += 8)
            o[(size_t)(n0 + r) * KSZ + k0 + tx] = __float2half_rn(tile[tx][r]);
    } else {
        const size_t i = (size_t)(bi - 2 * WT_BLOCKS) * 256 + threadIdx.x;
        float4 v = ((const float4*)h)[i];
        ((__half2*)af)[2 * i]     = __floats2half2_rn(v.x, v.y);
        ((__half2*)af)[2 * i + 1] = __floats2half2_rn(v.z, v.w);
    }
}

// ---------------------------------------------------------------------------
// Scan phase 1 (2 channels/thread): P = prod cf, S = chunk-local scan end.
// ---------------------------------------------------------------------------
__global__ void __launch_bounds__(256)
scan_p1(const __half* __restrict__ z, float* __restrict__ cP, float* __restrict__ cS)
{
    const int idx = blockIdx.x * blockDim.x + threadIdx.x;   // B*NC*512
    const int cp2 = idx & 511;
    const int chunk = (idx >> 9) & (NC - 1);
    const int b = idx >> 15;                                 // 9 + log2(NC)=6
    const __half* zb = z + ((size_t)b * TLEN + (size_t)chunk * CL) * N3H + cp2 * 2;
    float P0 = 1.0f, S0 = 0.0f, P1 = 1.0f, S1 = 0.0f;
    #pragma unroll 8
    for (int t = 0; t < CL; ++t) {
        float2 gv = __half22float2(*(const __half2*)(zb + (size_t)t * N3H));
        float2 cf = __half22float2(*(const __half2*)(zb + (size_t)t * N3H + HDIM));
        S0 = fmaf(cf.x, S0, (1.0f - cf.x) * gv.x);  P0 *= cf.x;
        S1 = fmaf(cf.y, S1, (1.0f - cf.y) * gv.y);  P1 *= cf.y;
    }
    const size_t o = (((size_t)(b * NC + chunk)) << 10) + cp2 * 2;
    *(float2*)(cP + o) = make_float2(P0, P1);
    *(float2*)(cS + o) = make_float2(S0, S1);
}

// ---------------------------------------------------------------------------
// Scan phase 3 (2 channels/thread) with inline carry compose.
// h0 read from fp16 hin (== af in both layers).
// layer==0: write fp16 af. layer==1: write fp32 out.
// ---------------------------------------------------------------------------
__global__ void __launch_bounds__(256)
scan_p3(const __half* __restrict__ z, const __half* __restrict__ hin,
        const float* __restrict__ cP, const float* __restrict__ cS,
        float* __restrict__ out32, __half* __restrict__ oa16, int layer)
{
    const int idx = blockIdx.x * blockDim.x + threadIdx.x;   // B*NC*512
    const int cp2 = idx & 511;
    const int chunk = (idx >> 9) & (NC - 1);
    const int b = idx >> 15;
    const size_t row0 = (size_t)b * TLEN + (size_t)chunk * CL;
    const __half* zb = z + row0 * N3H + cp2 * 2;

    // inline carry compose
    float s0 = 0.0f, s1 = 0.0f;
    for (int j = 0; j < chunk; ++j) {
        const size_t o = (((size_t)(b * NC + j)) << 10) + cp2 * 2;
        float2 P = *(const float2*)(cP + o);
        float2 S = *(const float2*)(cS + o);
        s0 = fmaf(P.x, s0, S.x);
        s1 = fmaf(P.y, s1, S.y);
    }

    #pragma unroll 4
    for (int t = 0; t < CL; ++t) {
        float2 gv = __half22float2(*(const __half2*)(zb + (size_t)t * N3H));
        float2 cf = __half22float2(*(const __half2*)(zb + (size_t)t * N3H + HDIM));
        float2 gp = __half22float2(*(const __half2*)(zb + (size_t)t * N3H + 2 * HDIM));
        const size_t ho = (row0 + t) * HDIM + cp2 * 2;
        float2 h0 = __half22float2(*(const __half2*)(hin + ho));

        s0 = fmaf(cf.x, s0, (1.0f - cf.x) * gv.x);
        s1 = fmaf(cf.y, s1, (1.0f - cf.y) * gv.y);

        float o0 = fmaf(gp.x, s0 - h0.x, h0.x);
        float o1 = fmaf(gp.y, s1 - h0.y, h0.y);

        if (layer == 0)
            *(__half2*)(oa16 + ho) = __floats2half2_rn(o0, o1);
        else
            *(float2*)(out32 + ho) = make_float2(o0, o1);
    }
}

// ---------------------------------------------------------------------------
extern "C" void kernel_launch(void* const* d_in, const int* in_sizes, int n_in,
                              void* d_out, int out_size)
{
    const float* h  = (const float*)d_in[0];
    const float* W0 = (const float*)d_in[1];
    const float* W1 = (const float*)d_in[2];
    float* out = (float*)d_out;

    float *cP, *cS;
    __half *zbuf, *af, *w0t, *w1t;
    cudaGetSymbolAddress((void**)&zbuf, g_z);
    cudaGetSymbolAddress((void**)&af, g_af);
    cudaGetSymbolAddress((void**)&w0t, g_w0);
    cudaGetSymbolAddress((void**)&w1t, g_w1);
    cudaGetSymbolAddress((void**)&cP, g_cP);
    cudaGetSymbolAddress((void**)&cS, g_cS);

    cudaFuncSetAttribute(gemm_f16,
                         cudaFuncAttributeMaxDynamicSharedMemorySize, SMEM_DYN);

    const dim3 ggrid(N3H / GM_BN, MROWS / GM_BM);        // (24, 256)
    const int p1_blocks = (BSZ * NC * HDIM / 2) / 256;   // 1024

    prep_kernel<<<2 * WT_BLOCKS + CA_BLOCKS, 256>>>(W0, W1, h, w0t, w1t, af);

    // ---- layer 0 ----
    gemm_f16<<<ggrid, 256, SMEM_DYN>>>(af, w0t, zbuf);
    scan_p1<<<p1_blocks, 256>>>(zbuf, cP, cS);
    scan_p3<<<p1_blocks, 256>>>(zbuf, af, cP, cS, (float*)0, af, 0);

    // ---- layer 1 ----
    gemm_f16<<<ggrid, 256, SMEM_DYN>>>(af, w1t, zbuf);
    scan_p1<<<p1_blocks, 256>>>(zbuf, cP, cS);
    scan_p3<<<p1_blocks, 256>>>(zbuf, af, cP, cS, out, (__half*)0, 1);
}

// round 16
// speedup vs baseline: 1.0123x; 1.0123x over previous
#include <cuda_runtime.h>
#include <cuda_fp16.h>
#include <cstdint>

// ---------------------------------------------------------------------------
// Problem constants
// ---------------------------------------------------------------------------
#define BSZ   8
#define TLEN  4096
#define HDIM  1024
#define N3H   3072
#define KSZ   1024
#define MROWS (BSZ * TLEN)      // 32768
#define NC    64                // scan chunks per sequence
#define CL    (TLEN / NC)       // 64 steps per chunk

// ---------------------------------------------------------------------------
// Device scratch (no allocations allowed)
// ---------------------------------------------------------------------------
__device__ __half g_z [(size_t)MROWS * N3H];      // transformed gates (fp16)
                                                  // [0..1023]=gv [1024..2047]=cf [2048..]=gp
__device__ __half g_af[(size_t)MROWS * KSZ];      // A fp16 [M,K]; also inter-layer h
__device__ __half g_w0[(size_t)N3H * KSZ];        // W0^T fp16 [N,K]
__device__ __half g_w1[(size_t)N3H * KSZ];        // W1^T fp16 [N,K]
__device__ float  g_cP[(size_t)BSZ * NC * HDIM];  // chunk coeff product
__device__ float  g_cS[(size_t)BSZ * NC * HDIM];  // chunk local scan end

// ---------------------------------------------------------------------------
// Helpers
// ---------------------------------------------------------------------------
__device__ __forceinline__ uint32_t smem_u32(const void* p) {
    uint32_t a;
    asm("{ .reg .u64 t; cvta.to.shared.u64 t, %1; cvt.u32.u64 %0, t; }"
        : "=r"(a) : "l"(p));
    return a;
}

__device__ __forceinline__ void cp16(uint32_t dst, const void* src) {
    asm volatile("cp.async.cg.shared.global [%0], [%1], 16;" :: "r"(dst), "l"(src));
}

__device__ __forceinline__ void ldsm4(uint32_t r[4], uint32_t addr) {
    asm volatile("ldmatrix.sync.aligned.m8n8.x4.shared.b16 {%0,%1,%2,%3}, [%4];"
        : "=r"(r[0]), "=r"(r[1]), "=r"(r[2]), "=r"(r[3]) : "r"(addr));
}

__device__ __forceinline__ void mma_f16(float c[4], const uint32_t a[4],
                                        uint32_t b0, uint32_t b1) {
    asm volatile(
        "mma.sync.aligned.m16n8k16.row.col.f32.f16.f16.f32 "
        "{%0,%1,%2,%3}, {%4,%5,%6,%7}, {%8,%9}, {%0,%1,%2,%3};"
        : "+f"(c[0]), "+f"(c[1]), "+f"(c[2]), "+f"(c[3])
        : "r"(a[0]), "r"(a[1]), "r"(a[2]), "r"(a[3]), "r"(b0), "r"(b1));
}

__device__ __forceinline__ float fsig(float x) {
    return __fdividef(1.0f, 1.0f + __expf(-x));
}

// streaming (evict-first) half2 load
__device__ __forceinline__ float2 ld_h2_cs(const __half* p) {
    uint32_t v;
    asm volatile("ld.global.cs.b32 %0, [%1];" : "=r"(v) : "l"(p));
    return __half22float2(*(__half2*)&v);
}

// per-section gate transform (GEMM epilogue)
__device__ __forceinline__ float gate_xform(float v, int mode) {
    if (mode == 0) return (v >= 0.0f) ? (v + 0.5f) : fsig(v);
    if (mode == 1) return __fdividef(1.0f, 1.0f + __expf(v));
    return fsig(v);
}

// ---------------------------------------------------------------------------
// GEMM: z'[M,3H] = xform(A[M,K] * W[K,3H]), fp16 in, fp32 acc, fp16 out.
// Tile 128x128, BK=32, 4-stage cp.async, 8 warps x (64x32), 2 CTAs/SM.
// (R13-validated configuration.)
// ---------------------------------------------------------------------------
#define GM_BM 128
#define GM_BN 128
#define GM_BK 32
#define STAGES 4
#define KITERS (KSZ / GM_BK)            // 32
#define OPB 8192
#define STB (2 * OPB)
#define SMEM_DYN (STAGES * STB)         // 64 KB

__device__ __forceinline__ uint32_t sw_off(int slice, int r, int g) {
    return (uint32_t)(((slice * 128 + r) * 2 + (g ^ ((r >> 2) & 1))) * 16);
}

__device__ __forceinline__ void load_stage(
    uint32_t sbase, int stage,
    const __half* __restrict__ A, const __half* __restrict__ B,
    int bm, int bn, int kt, int tid)
{
    const int k0 = kt * GM_BK;
    const uint32_t st = sbase + (uint32_t)stage * STB;
    #pragma unroll
    for (int i = 0; i < 4; ++i) {
        const int idx = tid + i * 256;
        const int op = idx >> 9;
        const int j = idx & 511;
        const int r = j >> 2, slice = (j >> 1) & 1, g = j & 1;
        const __half* base = op ? B : A;
        const int grow = (op ? bn : bm) + r;
        const void* src = base + (size_t)grow * KSZ + k0 + slice * 16 + g * 8;
        cp16(st + (uint32_t)op * OPB + sw_off(slice, r, g), src);
    }
    asm volatile("cp.async.commit_group;" ::: "memory");
}

__global__ void __launch_bounds__(256, 2)
gemm_f16(const __half* __restrict__ A, const __half* __restrict__ B,
         __half* __restrict__ C)
{
    extern __shared__ char dsm[];
    const uint32_t sbase = smem_u32(dsm);

    const int tid  = threadIdx.x;
    const int lane = tid & 31;
    const int wid  = tid >> 5;
    const int wm   = wid >> 2;
    const int wn   = wid & 3;
    const int bm   = blockIdx.y * GM_BM;
    const int bn   = blockIdx.x * GM_BN;

    const int rowA = (lane & 7) + ((lane >> 3) & 1) * 8;
    const int gA   = lane >> 4;
    const int rowB = (lane & 7) + (lane >> 4) * 8;
    const int gB   = (lane >> 3) & 1;

    float acc[4][4][4];
    #pragma unroll
    for (int i = 0; i < 4; ++i)
        #pragma unroll
        for (int j = 0; j < 4; ++j)
            #pragma unroll
            for (int q = 0; q < 4; ++q) acc[i][j][q] = 0.0f;

    #pragma unroll
    for (int s = 0; s < STAGES - 1; ++s)
        load_stage(sbase, s, A, B, bm, bn, s, tid);

    for (int kt = 0; kt < KITERS; ++kt) {
        asm volatile("cp.async.wait_group %0;" :: "n"(STAGES - 2) : "memory");
        __syncthreads();

        if (kt + STAGES - 1 < KITERS)
            load_stage(sbase, (kt + STAGES - 1) & (STAGES - 1),
                       A, B, bm, bn, kt + STAGES - 1, tid);

        const uint32_t st = sbase + (uint32_t)(kt & (STAGES - 1)) * STB;

        #pragma unroll
        for (int slice = 0; slice < 2; ++slice) {
            uint32_t af[4][4];
            #pragma unroll
            for (int mf = 0; mf < 4; ++mf) {
                const uint32_t off = sw_off(slice, wm * 64 + mf * 16 + rowA, gA);
                ldsm4(af[mf], st + off);
            }
            #pragma unroll
            for (int n16 = 0; n16 < 2; ++n16) {
                uint32_t bf[4];
                const uint32_t offB = sw_off(slice, wn * 32 + n16 * 16 + rowB, gB);
                ldsm4(bf, st + OPB + offB);
                #pragma unroll
                for (int mf = 0; mf < 4; ++mf)
                    #pragma unroll
                    for (int h = 0; h < 2; ++h)
                        mma_f16(acc[mf][n16 * 2 + h], af[mf],
                                bf[2 * h], bf[2 * h + 1]);
            }
        }
    }

    const int mode = bn >> 10;           // 0=hidden 1=gate 2=proj
    #pragma unroll
    for (int mf = 0; mf < 4; ++mf) {
        const int row = bm + wm * 64 + mf * 16 + (lane >> 2);
        #pragma unroll
        for (int nf = 0; nf < 4; ++nf) {
            const float* c = acc[mf][nf];
            const int col = bn + wn * 32 + (nf >> 1) * 16 + (nf & 1) * 8 + (lane & 3) * 2;
            float t0 = gate_xform(c[0], mode), t1 = gate_xform(c[1], mode);
            float t2 = gate_xform(c[2], mode), t3 = gate_xform(c[3], mode);
            *(__half2*)(C + (size_t)row * N3H + col)       = __floats2half2_rn(t0, t1);
            *(__half2*)(C + (size_t)(row + 8) * N3H + col) = __floats2half2_rn(t2, t3);
        }
    }
}

// ---------------------------------------------------------------------------
// Fused prologue: transpose+convert W0 and W1, convert A -> fp16.
// ---------------------------------------------------------------------------
#define WT_BLOCKS 3072
#define CA_BLOCKS 32768

__global__ void __launch_bounds__(256)
prep_kernel(const float* __restrict__ W0, const float* __restrict__ W1,
            const float* __restrict__ h,
            __half* __restrict__ w0t, __half* __restrict__ w1t,
            __half* __restrict__ af)
{
    const int bi = blockIdx.x;
    if (bi < 2 * WT_BLOCKS) {
        __shared__ float tile[32][33];
        const float* W = (bi < WT_BLOCKS) ? W0 : W1;
        __half* o = (bi < WT_BLOCKS) ? w0t : w1t;
        const int lb = (bi < WT_BLOCKS) ? bi : bi - WT_BLOCKS;
        const int n0 = (lb % 96) * 32;
        const int k0 = (lb / 96) * 32;
        const int tx = threadIdx.x & 31, ty = threadIdx.x >> 5;
        #pragma unroll
        for (int r = ty; r < 32; r += 8)
            tile[r][tx] = W[(size_t)(k0 + r) * N3H + n0 + tx];
        __syncthreads();
        #pragma unroll
        for (int r = ty; r < 32; r += 8)
            o[(size_t)(n0 + r) * KSZ + k0 + tx] = __float2half_rn(tile[tx][r]);
    } else {
        const size_t i = (size_t)(bi - 2 * WT_BLOCKS) * 256 + threadIdx.x;
        float4 v = ((const float4*)h)[i];
        ((__half2*)af)[2 * i]     = __floats2half2_rn(v.x, v.y);
        ((__half2*)af)[2 * i + 1] = __floats2half2_rn(v.z, v.w);
    }
}

// ---------------------------------------------------------------------------
// Scan phase 1 (2 channels/thread): P = prod cf, S = chunk-local scan end.
// ---------------------------------------------------------------------------
__global__ void __launch_bounds__(256)
scan_p1(const __half* __restrict__ z, float* __restrict__ cP, float* __restrict__ cS)
{
    const int idx = blockIdx.x * blockDim.x + threadIdx.x;   // B*NC*512
    const int cp2 = idx & 511;
    const int chunk = (idx >> 9) & (NC - 1);
    const int b = idx >> 15;                                 // 9 + log2(64)
    const __half* zb = z + ((size_t)b * TLEN + (size_t)chunk * CL) * N3H + cp2 * 2;
    float P0 = 1.0f, S0 = 0.0f, P1 = 1.0f, S1 = 0.0f;
    #pragma unroll 8
    for (int t = 0; t < CL; ++t) {
        float2 gv = __half22float2(*(const __half2*)(zb + (size_t)t * N3H));
        float2 cf = __half22float2(*(const __half2*)(zb + (size_t)t * N3H + HDIM));
        S0 = fmaf(cf.x, S0, (1.0f - cf.x) * gv.x);  P0 *= cf.x;
        S1 = fmaf(cf.y, S1, (1.0f - cf.y) * gv.y);  P1 *= cf.y;
    }
    const size_t o = (((size_t)(b * NC + chunk)) << 10) + cp2 * 2;
    *(float2*)(cP + o) = make_float2(P0, P1);
    *(float2*)(cS + o) = make_float2(S0, S1);
}

// ---------------------------------------------------------------------------
// Scan phase 3 (2 channels/thread) with inline carry compose.
// z read with streaming hint (last reader). h0 from fp16 hin (== af).
// layer==0: write fp16 af. layer==1: write fp32 out.
// ---------------------------------------------------------------------------
__global__ void __launch_bounds__(256)
scan_p3(const __half* __restrict__ z, const __half* __restrict__ hin,
        const float* __restrict__ cP, const float* __restrict__ cS,
        float* __restrict__ out32, __half* __restrict__ oa16, int layer)
{
    const int idx = blockIdx.x * blockDim.x + threadIdx.x;   // B*NC*512
    const int cp2 = idx & 511;
    const int chunk = (idx >> 9) & (NC - 1);
    const int b = idx >> 15;
    const size_t row0 = (size_t)b * TLEN + (size_t)chunk * CL;
    const __half* zb = z + row0 * N3H + cp2 * 2;

    // inline carry compose
    float s0 = 0.0f, s1 = 0.0f;
    for (int j = 0; j < chunk; ++j) {
        const size_t o = (((size_t)(b * NC + j)) << 10) + cp2 * 2;
        float2 P = *(const float2*)(cP + o);
        float2 S = *(const float2*)(cS + o);
        s0 = fmaf(P.x, s0, S.x);
        s1 = fmaf(P.y, s1, S.y);
    }

    #pragma unroll 4
    for (int t = 0; t < CL; ++t) {
        float2 gv = ld_h2_cs(zb + (size_t)t * N3H);
        float2 cf = ld_h2_cs(zb + (size_t)t * N3H + HDIM);
        float2 gp = ld_h2_cs(zb + (size_t)t * N3H + 2 * HDIM);
        const size_t ho = (row0 + t) * HDIM + cp2 * 2;
        float2 h0 = __half22float2(*(const __half2*)(hin + ho));

        s0 = fmaf(cf.x, s0, (1.0f - cf.x) * gv.x);
        s1 = fmaf(cf.y, s1, (1.0f - cf.y) * gv.y);

        float o0 = fmaf(gp.x, s0 - h0.x, h0.x);
        float o1 = fmaf(gp.y, s1 - h0.y, h0.y);

        if (layer == 0)
            *(__half2*)(oa16 + ho) = __floats2half2_rn(o0, o1);
        else
            *(float2*)(out32 + ho) = make_float2(o0, o1);
    }
}

// ---------------------------------------------------------------------------
extern "C" void kernel_launch(void* const* d_in, const int* in_sizes, int n_in,
                              void* d_out, int out_size)
{
    const float* h  = (const float*)d_in[0];
    const float* W0 = (const float*)d_in[1];
    const float* W1 = (const float*)d_in[2];
    float* out = (float*)d_out;

    float *cP, *cS;
    __half *zbuf, *af, *w0t, *w1t;
    cudaGetSymbolAddress((void**)&zbuf, g_z);
    cudaGetSymbolAddress((void**)&af, g_af);
    cudaGetSymbolAddress((void**)&w0t, g_w0);
    cudaGetSymbolAddress((void**)&w1t, g_w1);
    cudaGetSymbolAddress((void**)&cP, g_cP);
    cudaGetSymbolAddress((void**)&cS, g_cS);

    cudaFuncSetAttribute(gemm_f16,
                         cudaFuncAttributeMaxDynamicSharedMemorySize, SMEM_DYN);

    const dim3 ggrid(N3H / GM_BN, MROWS / GM_BM);        // (24, 256)
    const int p1_blocks = (BSZ * NC * HDIM / 2) / 256;   // 1024

    prep_kernel<<<2 * WT_BLOCKS + CA_BLOCKS, 256>>>(W0, W1, h, w0t, w1t, af);

    // ---- layer 0 ----
    gemm_f16<<<ggrid, 256, SMEM_DYN>>>(af, w0t, zbuf);
    scan_p1<<<p1_blocks, 256>>>(zbuf, cP, cS);
    scan_p3<<<p1_blocks, 256>>>(zbuf, af, cP, cS, (float*)0, af, 0);

    // ---- layer 1 ----
    gemm_f16<<<ggrid, 256, SMEM_DYN>>>(af, w1t, zbuf);
    scan_p1<<<p1_blocks, 256>>>(zbuf, cP, cS);
    scan_p3<<<p1_blocks, 256>>>(zbuf, af, cP, cS, out, (__half*)0, 1);
}

// round 17
// speedup vs baseline: 1.0146x; 1.0022x over previous
#include <cuda_runtime.h>
#include <cuda_fp16.h>
#include <cstdint>

// ---------------------------------------------------------------------------
// Problem constants
// ---------------------------------------------------------------------------
#define BSZ   8
#define TLEN  4096
#define HDIM  1024
#define N3H   3072
#define KSZ   1024
#define MROWS (BSZ * TLEN)      // 32768
#define NC    64                // scan chunks per sequence
#define CL    (TLEN / NC)       // 64 steps per chunk

// ---------------------------------------------------------------------------
// Device scratch (no allocations allowed)
// ---------------------------------------------------------------------------
__device__ __half g_z [(size_t)MROWS * N3H];      // transformed gates (fp16)
                                                  // [0..1023]=gv [1024..2047]=cf [2048..]=gp
__device__ __half g_af[(size_t)MROWS * KSZ];      // A fp16 [M,K]; also inter-layer h
__device__ __half g_w0[(size_t)N3H * KSZ];        // W0^T fp16 [N,K]
__device__ __half g_w1[(size_t)N3H * KSZ];        // W1^T fp16 [N,K]
__device__ float  g_cP[(size_t)BSZ * NC * HDIM];  // chunk coeff product
__device__ float  g_cS[(size_t)BSZ * NC * HDIM];  // chunk local scan end

// ---------------------------------------------------------------------------
// Helpers
// ---------------------------------------------------------------------------
__device__ __forceinline__ uint32_t smem_u32(const void* p) {
    uint32_t a;
    asm("{ .reg .u64 t; cvta.to.shared.u64 t, %1; cvt.u32.u64 %0, t; }"
        : "=r"(a) : "l"(p));
    return a;
}

__device__ __forceinline__ void cp16(uint32_t dst, const void* src) {
    asm volatile("cp.async.cg.shared.global [%0], [%1], 16;" :: "r"(dst), "l"(src));
}

__device__ __forceinline__ void ldsm4(uint32_t r[4], uint32_t addr) {
    asm volatile("ldmatrix.sync.aligned.m8n8.x4.shared.b16 {%0,%1,%2,%3}, [%4];"
        : "=r"(r[0]), "=r"(r[1]), "=r"(r[2]), "=r"(r[3]) : "r"(addr));
}

__device__ __forceinline__ void mma_f16(float c[4], const uint32_t a[4],
                                        uint32_t b0, uint32_t b1) {
    asm volatile(
        "mma.sync.aligned.m16n8k16.row.col.f32.f16.f16.f32 "
        "{%0,%1,%2,%3}, {%4,%5,%6,%7}, {%8,%9}, {%0,%1,%2,%3};"
        : "+f"(c[0]), "+f"(c[1]), "+f"(c[2]), "+f"(c[3])
        : "r"(a[0]), "r"(a[1]), "r"(a[2]), "r"(a[3]), "r"(b0), "r"(b1));
}

__device__ __forceinline__ float fsig(float x) {
    return __fdividef(1.0f, 1.0f + __expf(-x));
}

// per-section gate transform (GEMM epilogue)
__device__ __forceinline__ float gate_xform(float v, int mode) {
    if (mode == 0) return (v >= 0.0f) ? (v + 0.5f) : fsig(v);
    if (mode == 1) return __fdividef(1.0f, 1.0f + __expf(v));
    return fsig(v);
}

// ---------------------------------------------------------------------------
// GEMM: z'[M,3H] = xform(A[M,K] * W[K,3H]), fp16 in, fp32 acc, fp16 out.
// Tile 128x128, BK=32, 4-stage cp.async, 8 warps x (64x32), 2 CTAs/SM.
// (R13-validated configuration.)
// ---------------------------------------------------------------------------
#define GM_BM 128
#define GM_BN 128
#define GM_BK 32
#define STAGES 4
#define KITERS (KSZ / GM_BK)            // 32
#define OPB 8192
#define STB (2 * OPB)
#define SMEM_DYN (STAGES * STB)         // 64 KB

__device__ __forceinline__ uint32_t sw_off(int slice, int r, int g) {
    return (uint32_t)(((slice * 128 + r) * 2 + (g ^ ((r >> 2) & 1))) * 16);
}

__device__ __forceinline__ void load_stage(
    uint32_t sbase, int stage,
    const __half* __restrict__ A, const __half* __restrict__ B,
    int bm, int bn, int kt, int tid)
{
    const int k0 = kt * GM_BK;
    const uint32_t st = sbase + (uint32_t)stage * STB;
    #pragma unroll
    for (int i = 0; i < 4; ++i) {
        const int idx = tid + i * 256;
        const int op = idx >> 9;
        const int j = idx & 511;
        const int r = j >> 2, slice = (j >> 1) & 1, g = j & 1;
        const __half* base = op ? B : A;
        const int grow = (op ? bn : bm) + r;
        const void* src = base + (size_t)grow * KSZ + k0 + slice * 16 + g * 8;
        cp16(st + (uint32_t)op * OPB + sw_off(slice, r, g), src);
    }
    asm volatile("cp.async.commit_group;" ::: "memory");
}

__global__ void __launch_bounds__(256, 2)
gemm_f16(const __half* __restrict__ A, const __half* __restrict__ B,
         __half* __restrict__ C)
{
    extern __shared__ char dsm[];
    const uint32_t sbase = smem_u32(dsm);

    const int tid  = threadIdx.x;
    const int lane = tid & 31;
    const int wid  = tid >> 5;
    const int wm   = wid >> 2;
    const int wn   = wid & 3;
    const int bm   = blockIdx.y * GM_BM;
    const int bn   = blockIdx.x * GM_BN;

    const int rowA = (lane & 7) + ((lane >> 3) & 1) * 8;
    const int gA   = lane >> 4;
    const int rowB = (lane & 7) + (lane >> 4) * 8;
    const int gB   = (lane >> 3) & 1;

    float acc[4][4][4];
    #pragma unroll
    for (int i = 0; i < 4; ++i)
        #pragma unroll
        for (int j = 0; j < 4; ++j)
            #pragma unroll
            for (int q = 0; q < 4; ++q) acc[i][j][q] = 0.0f;

    #pragma unroll
    for (int s = 0; s < STAGES - 1; ++s)
        load_stage(sbase, s, A, B, bm, bn, s, tid);

    for (int kt = 0; kt < KITERS; ++kt) {
        asm volatile("cp.async.wait_group %0;" :: "n"(STAGES - 2) : "memory");
        __syncthreads();

        if (kt + STAGES - 1 < KITERS)
            load_stage(sbase, (kt + STAGES - 1) & (STAGES - 1),
                       A, B, bm, bn, kt + STAGES - 1, tid);

        const uint32_t st = sbase + (uint32_t)(kt & (STAGES - 1)) * STB;

        #pragma unroll
        for (int slice = 0; slice < 2; ++slice) {
            uint32_t af[4][4];
            #pragma unroll
            for (int mf = 0; mf < 4; ++mf) {
                const uint32_t off = sw_off(slice, wm * 64 + mf * 16 + rowA, gA);
                ldsm4(af[mf], st + off);
            }
            #pragma unroll
            for (int n16 = 0; n16 < 2; ++n16) {
                uint32_t bf[4];
                const uint32_t offB = sw_off(slice, wn * 32 + n16 * 16 + rowB, gB);
                ldsm4(bf, st + OPB + offB);
                #pragma unroll
                for (int mf = 0; mf < 4; ++mf)
                    #pragma unroll
                    for (int h = 0; h < 2; ++h)
                        mma_f16(acc[mf][n16 * 2 + h], af[mf],
                                bf[2 * h], bf[2 * h + 1]);
            }
        }
    }

    const int mode = bn >> 10;           // 0=hidden 1=gate 2=proj
    #pragma unroll
    for (int mf = 0; mf < 4; ++mf) {
        const int row = bm + wm * 64 + mf * 16 + (lane >> 2);
        #pragma unroll
        for (int nf = 0; nf < 4; ++nf) {
            const float* c = acc[mf][nf];
            const int col = bn + wn * 32 + (nf >> 1) * 16 + (nf & 1) * 8 + (lane & 3) * 2;
            float t0 = gate_xform(c[0], mode), t1 = gate_xform(c[1], mode);
            float t2 = gate_xform(c[2], mode), t3 = gate_xform(c[3], mode);
            *(__half2*)(C + (size_t)row * N3H + col)       = __floats2half2_rn(t0, t1);
            *(__half2*)(C + (size_t)(row + 8) * N3H + col) = __floats2half2_rn(t2, t3);
        }
    }
}

// ---------------------------------------------------------------------------
// Fused prologue: transpose+convert W0 and W1, convert A -> fp16.
// ---------------------------------------------------------------------------
#define WT_BLOCKS 3072
#define CA_BLOCKS 32768

__global__ void __launch_bounds__(256)
prep_kernel(const float* __restrict__ W0, const float* __restrict__ W1,
            const float* __restrict__ h,
            __half* __restrict__ w0t, __half* __restrict__ w1t,
            __half* __restrict__ af)
{
    const int bi = blockIdx.x;
    if (bi < 2 * WT_BLOCKS) {
        __shared__ float tile[32][33];
        const float* W = (bi < WT_BLOCKS) ? W0 : W1;
        __half* o = (bi < WT_BLOCKS) ? w0t : w1t;
        const int lb = (bi < WT_BLOCKS) ? bi : bi - WT_BLOCKS;
        const int n0 = (lb % 96) * 32;
        const int k0 = (lb / 96) * 32;
        const int tx = threadIdx.x & 31, ty = threadIdx.x >> 5;
        #pragma unroll
        for (int r = ty; r < 32; r += 8)
            tile[r][tx] = W[(size_t)(k0 + r) * N3H + n0 + tx];
        __syncthreads();
        #pragma unroll
        for (int r = ty; r < 32; r += 8)
            o[(size_t)(n0 + r) * KSZ + k0 + tx] = __float2half_rn(tile[tx][r]);
    } else {
        const size_t i = (size_t)(bi - 2 * WT_BLOCKS) * 256 + threadIdx.x;
        float4 v = ((const float4*)h)[i];
        ((__half2*)af)[2 * i]     = __floats2half2_rn(v.x, v.y);
        ((__half2*)af)[2 * i + 1] = __floats2half2_rn(v.z, v.w);
    }
}

// ---------------------------------------------------------------------------
// Scan phase 1 (2 channels/thread): P = prod cf, S = chunk-local scan end.
// ---------------------------------------------------------------------------
__global__ void __launch_bounds__(256)
scan_p1(const __half* __restrict__ z, float* __restrict__ cP, float* __restrict__ cS)
{
    const int idx = blockIdx.x * blockDim.x + threadIdx.x;   // B*NC*512
    const int cp2 = idx & 511;
    const int chunk = (idx >> 9) & (NC - 1);
    const int b = idx >> 15;                                 // 9 + log2(64)
    const __half* zb = z + ((size_t)b * TLEN + (size_t)chunk * CL) * N3H + cp2 * 2;
    float P0 = 1.0f, S0 = 0.0f, P1 = 1.0f, S1 = 0.0f;
    #pragma unroll 8
    for (int t = 0; t < CL; ++t) {
        float2 gv = __half22float2(*(const __half2*)(zb + (size_t)t * N3H));
        float2 cf = __half22float2(*(const __half2*)(zb + (size_t)t * N3H + HDIM));
        S0 = fmaf(cf.x, S0, (1.0f - cf.x) * gv.x);  P0 *= cf.x;
        S1 = fmaf(cf.y, S1, (1.0f - cf.y) * gv.y);  P1 *= cf.y;
    }
    const size_t o = (((size_t)(b * NC + chunk)) << 10) + cp2 * 2;
    *(float2*)(cP + o) = make_float2(P0, P1);
    *(float2*)(cS + o) = make_float2(S0, S1);
}

// ---------------------------------------------------------------------------
// Scan phase 3 (2 channels/thread) with inline carry compose.
// h0 from fp16 hin (== af). layer==0: write fp16 af. layer==1: write fp32 out.
// ---------------------------------------------------------------------------
__global__ void __launch_bounds__(256)
scan_p3(const __half* __restrict__ z, const __half* __restrict__ hin,
        const float* __restrict__ cP, const float* __restrict__ cS,
        float* __restrict__ out32, __half* __restrict__ oa16, int layer)
{
    const int idx = blockIdx.x * blockDim.x + threadIdx.x;   // B*NC*512
    const int cp2 = idx & 511;
    const int chunk = (idx >> 9) & (NC - 1);
    const int b = idx >> 15;
    const size_t row0 = (size_t)b * TLEN + (size_t)chunk * CL;
    const __half* zb = z + row0 * N3H + cp2 * 2;

    // inline carry compose
    float s0 = 0.0f, s1 = 0.0f;
    for (int j = 0; j < chunk; ++j) {
        const size_t o = (((size_t)(b * NC + j)) << 10) + cp2 * 2;
        float2 P = *(const float2*)(cP + o);
        float2 S = *(const float2*)(cS + o);
        s0 = fmaf(P.x, s0, S.x);
        s1 = fmaf(P.y, s1, S.y);
    }

    #pragma unroll 4
    for (int t = 0; t < CL; ++t) {
        float2 gv = __half22float2(*(const __half2*)(zb + (size_t)t * N3H));
        float2 cf = __half22float2(*(const __half2*)(zb + (size_t)t * N3H + HDIM));
        float2 gp = __half22float2(*(const __half2*)(zb + (size_t)t * N3H + 2 * HDIM));
        const size_t ho = (row0 + t) * HDIM + cp2 * 2;
        float2 h0 = __half22float2(*(const __half2*)(hin + ho));

        s0 = fmaf(cf.x, s0, (1.0f - cf.x) * gv.x);
        s1 = fmaf(cf.y, s1, (1.0f - cf.y) * gv.y);

        float o0 = fmaf(gp.x, s0 - h0.x, h0.x);
        float o1 = fmaf(gp.y, s1 - h0.y, h0.y);

        if (layer == 0)
            *(__half2*)(oa16 + ho) = __floats2half2_rn(o0, o1);
        else
            *(float2*)(out32 + ho) = make_float2(o0, o1);
    }
}

// ---------------------------------------------------------------------------
extern "C" void kernel_launch(void* const* d_in, const int* in_sizes, int n_in,
                              void* d_out, int out_size)
{
    const float* h  = (const float*)d_in[0];
    const float* W0 = (const float*)d_in[1];
    const float* W1 = (const float*)d_in[2];
    float* out = (float*)d_out;

    float *cP, *cS;
    __half *zbuf, *af, *w0t, *w1t;
    cudaGetSymbolAddress((void**)&zbuf, g_z);
    cudaGetSymbolAddress((void**)&af, g_af);
    cudaGetSymbolAddress((void**)&w0t, g_w0);
    cudaGetSymbolAddress((void**)&w1t, g_w1);
    cudaGetSymbolAddress((void**)&cP, g_cP);
    cudaGetSymbolAddress((void**)&cS, g_cS);

    cudaFuncSetAttribute(gemm_f16,
                         cudaFuncAttributeMaxDynamicSharedMemorySize, SMEM_DYN);

    const dim3 ggrid(N3H / GM_BN, MROWS / GM_BM);        // (24, 256)
    const int p1_blocks = (BSZ * NC * HDIM / 2) / 256;   // 1024

    prep_kernel<<<2 * WT_BLOCKS + CA_BLOCKS, 256>>>(W0, W1, h, w0t, w1t, af);

    // ---- layer 0 ----
    gemm_f16<<<ggrid, 256, SMEM_DYN>>>(af, w0t, zbuf);
    scan_p1<<<p1_blocks, 256>>>(zbuf, cP, cS);
    scan_p3<<<p1_blocks, 256>>>(zbuf, af, cP, cS, (float*)0, af, 0);

    // ---- layer 1 ----
    gemm_f16<<<ggrid, 256, SMEM_DYN>>>(af, w1t, zbuf);
    scan_p1<<<p1_blocks, 256>>>(zbuf, cP, cS);
    scan_p3<<<p1_blocks, 256>>>(zbuf, af, cP, cS, out, (__half*)0, 1);
}